// round 1
// baseline (speedup 1.0000x reference)
#include <cuda_runtime.h>
#include <cuda_bf16.h>
#include <cstdint>

// Problem shape (fixed by the dataset)
#define B_ 8
#define T_ 4096
#define F_ 512
#define ROWS_ (B_ * T_)

// Scratch (no allocations allowed) — device globals.
__device__ float g_z[ROWS_];       // linear scores (pre-sigmoid; monotone-equivalent for peaks)
__device__ int   g_pos[ROWS_];     // compaction destination per row, -1 if not a peak
__device__ int   g_hlens[B_];      // peak counts per batch

// ---------------------------------------------------------------------------
// Kernel A: z[row] = dot(feat[row,:], W)   (sigmoid+bias dropped: monotone)
// One warp per row; 512 floats = 4 float4 per lane.
__global__ void __launch_bounds__(256) k_gemv(const float* __restrict__ feat,
                                              const float* __restrict__ W) {
    int row  = blockIdx.x * (blockDim.x >> 5) + (threadIdx.x >> 5);
    int lane = threadIdx.x & 31;
    if (row >= ROWS_) return;

    const float4* fr = reinterpret_cast<const float4*>(feat + (size_t)row * F_);
    const float4* w4 = reinterpret_cast<const float4*>(W);

    float s = 0.f;
#pragma unroll
    for (int i = 0; i < F_ / 4 / 32; i++) {
        int idx = lane + i * 32;
        float4 a = fr[idx];
        float4 w = w4[idx];
        s += a.x * w.x + a.y * w.y + a.z * w.z + a.w * w.w;
    }
#pragma unroll
    for (int o = 16; o > 0; o >>= 1)
        s += __shfl_down_sync(0xFFFFFFFFu, s, o);
    if (lane == 0) g_z[row] = s;
}

// ---------------------------------------------------------------------------
// Kernel B: per-batch peak detection + stable exclusive scan -> g_pos, g_hlens
// One block of 1024 threads per batch; 4 elements per thread.
__global__ void __launch_bounds__(1024) k_peakscan() {
    int b = blockIdx.x;
    const float* zb = g_z + b * T_;
    int t0 = threadIdx.x * 4;

    int flags[4];
    int cnt = 0;
#pragma unroll
    for (int k = 0; k < 4; k++) {
        int t = t0 + k;
        float c = zb[t];
        float l = (t > 0)      ? zb[t - 1] : c;
        float r = (t < T_ - 1) ? zb[t + 1] : c;
        flags[k] = (c >= l) & (c >= r);
        cnt += flags[k];
    }

    // Block exclusive scan of per-thread cnt (32 warps).
    __shared__ int warp_sums[32];
    int lane = threadIdx.x & 31;
    int wid  = threadIdx.x >> 5;
    int v = cnt;
#pragma unroll
    for (int o = 1; o < 32; o <<= 1) {
        int n = __shfl_up_sync(0xFFFFFFFFu, v, o);
        if (lane >= o) v += n;
    }
    if (lane == 31) warp_sums[wid] = v;
    __syncthreads();
    if (wid == 0) {
        int s = warp_sums[lane];
#pragma unroll
        for (int o = 1; o < 32; o <<= 1) {
            int n = __shfl_up_sync(0xFFFFFFFFu, s, o);
            if (lane >= o) s += n;
        }
        warp_sums[lane] = s;  // inclusive scan of warp sums
    }
    __syncthreads();

    int excl = (v - cnt) + (wid > 0 ? warp_sums[wid - 1] : 0);
#pragma unroll
    for (int k = 0; k < 4; k++) {
        int t = t0 + k;
        if (flags[k]) g_pos[b * T_ + t] = excl++;
        else          g_pos[b * T_ + t] = -1;
    }
    if (threadIdx.x == 0) g_hlens[b] = warp_sums[31];
}

// ---------------------------------------------------------------------------
// Kernel C: compaction writer. One block per source row index (b,t):
//  - if peak: copy feat row (b,t) -> out row (b, pos)
//  - also own destination row t: if t >= hlens[b], zero it.
// Every output row is written exactly once.
__global__ void __launch_bounds__(128) k_write(const float* __restrict__ feat,
                                               float* __restrict__ out) {
    int row = blockIdx.x;           // b*T + t
    int b = row >> 12;              // T_ = 4096
    int t = row & (T_ - 1);
    int p  = g_pos[row];
    int hl = g_hlens[b];

    if (p >= 0) {
        const float4* s = reinterpret_cast<const float4*>(feat + (size_t)row * F_);
        float4* d = reinterpret_cast<float4*>(out + ((size_t)b * T_ + p) * F_);
        d[threadIdx.x] = s[threadIdx.x];        // 128 threads * float4 = 512 floats
    }
    if (t >= hl) {
        float4* d = reinterpret_cast<float4*>(out + (size_t)row * F_);
        d[threadIdx.x] = make_float4(0.f, 0.f, 0.f, 0.f);
    }
}

// Kernel D: append hlens (as float) after feat_new, if out buffer includes it.
__global__ void k_hlens_tail(float* __restrict__ out) {
    int i = threadIdx.x;
    if (i < B_) out[(size_t)ROWS_ * F_ + i] = (float)g_hlens[i];
}

extern "C" void kernel_launch(void* const* d_in, const int* in_sizes, int n_in,
                              void* d_out, int out_size) {
    const float* feat = (const float*)d_in[0];
    const float* W    = (const float*)d_in[1];
    float* out        = (float*)d_out;

    // A: GEMV — 8 warps/block, 256 threads -> 4096 blocks
    k_gemv<<<ROWS_ / 8, 256>>>(feat, W);
    // B: peaks + scan — one block per batch
    k_peakscan<<<B_, 1024>>>();
    // C: compaction + zero-fill
    k_write<<<ROWS_, 128>>>(feat, out);
    // D: hlens tail if present in output buffer
    if (out_size >= ROWS_ * F_ + B_)
        k_hlens_tail<<<1, 32>>>(out);
}